// round 2
// baseline (speedup 1.0000x reference)
#include <cuda_runtime.h>

#define BATCH 64
#define NJ 21
#define BJ (BATCH * NJ)        // 1344
#define IMG 256

// Seeds: (sx, sy) per (batch, joint)
__device__ int2 g_seeds[BJ];

// w[d] = exp(-d^2 / (2 * 2.5^2)) = exp(-d^2 / 12.5), d = 0..5
__constant__ float c_w[6] = {
    1.0f,
    0.92311634638663580f,   // exp(-0.08)
    0.72614903707369090f,   // exp(-0.32)
    0.48675225595997170f,   // exp(-0.72)
    0.27803730045319410f,   // exp(-1.28)
    0.13533528323661270f    // exp(-2.00)
};

__global__ void seed_kernel(const float* __restrict__ joint) {
    int i = blockIdx.x * blockDim.x + threadIdx.x;
    if (i >= BJ) return;
    // Double precision projection: immune to fast-math substitution and
    // avoids sinf/cosf entirely (cos(atan2(y,x)) = x/rho, sin = y/rho).
    double x = (double)joint[i * 3 + 0];
    double y = (double)joint[i * 3 + 1];
    double z = (double)joint[i * 3 + 2];
    double rho = sqrt(x * x + y * y);
    double theta = atan2(rho, z);
    double r = 128.0 * theta / 1.5707963267948966;  // RADIUS * theta / (pi/2)
    double cphi, sphi;
    if (rho > 0.0) { cphi = x / rho; sphi = y / rho; }
    else           { cphi = 1.0;     sphi = 0.0;     }
    // rint = round-half-to-even, matching jnp.round
    double fx = rint(128.0 + r * cphi);
    double fy = rint(128.0 + r * sphi);
    int sx = (int)fx;
    int sy = (int)fy;
    sx = min(max(sx, 0), IMG - 1);
    sy = min(max(sy, 0), IMG - 1);
    g_seeds[i] = make_int2(sx, sy);
}

// Each thread writes 16 contiguous pixels (4x float4 = 64 bytes) of one row.
// Flat mapping over thread id t:
//   x0 = (t & 15) * 16, y = (t >> 4) & 255, bj = t >> 12
__global__ void __launch_bounds__(256) hm_kernel(float4* __restrict__ out) {
    unsigned t  = blockIdx.x * blockDim.x + threadIdx.x;
    unsigned x0 = (t & 15u) << 4;
    unsigned y  = (t >> 4) & 255u;
    unsigned bj = t >> 12;

    int2 s = g_seeds[bj];

    float4 v0 = make_float4(0.f, 0.f, 0.f, 0.f);
    float4 v1 = v0, v2 = v0, v3 = v0;

    int dy  = (int)y - s.y;
    int ady = dy < 0 ? -dy : dy;
    if (ady <= 5) {
        float wy = c_w[ady];
        float* vp[4] = {
            reinterpret_cast<float*>(&v0),
            reinterpret_cast<float*>(&v1),
            reinterpret_cast<float*>(&v2),
            reinterpret_cast<float*>(&v3)
        };
#pragma unroll
        for (int k = 0; k < 16; k++) {
            int dx  = (int)(x0 + k) - s.x;
            int adx = dx < 0 ? -dx : dx;
            if (adx <= 5) vp[k >> 2][k & 3] = wy * c_w[adx];
        }
    }

    float4* o = out + 4u * (size_t)t;
    __stcs(o + 0, v0);
    __stcs(o + 1, v1);
    __stcs(o + 2, v2);
    __stcs(o + 3, v3);
}

extern "C" void kernel_launch(void* const* d_in, const int* in_sizes, int n_in,
                              void* d_out, int out_size) {
    const float* joint = (const float*)d_in[0];

    // 1) project 1344 joints to pixel seeds
    seed_kernel<<<(BJ + 255) / 256, 256>>>(joint);

    // 2) write 64*21*256*256 floats, 16 per thread (64 B)
    //    total threads = 1344 * 256 * 16 = 5,505,024 -> 21504 blocks of 256
    const int total_threads = BJ * IMG * (IMG / 16);
    hm_kernel<<<total_threads / 256, 256>>>((float4*)d_out);
}

// round 3
// speedup vs baseline: 1.5876x; 1.5876x over previous
#include <cuda_runtime.h>

#define BATCH 64
#define NJ 21
#define BJ (BATCH * NJ)        // 1344
#define IMG 256

// w[d] = exp(-d^2 / (2 * 2.5^2)) = exp(-d^2 / 12.5), d = 0..5
__constant__ float c_w[6] = {
    1.0f,
    0.92311634638663580f,   // exp(-0.08)
    0.72614903707369090f,   // exp(-0.32)
    0.48675225595997170f,   // exp(-0.72)
    0.27803730045319410f,   // exp(-1.28)
    0.13533528323661270f    // exp(-2.00)
};

// One block = half of one (batch, joint) 256x256 map: 128 rows.
// 256 threads, each thread writes 32 float4 (lane-contiguous per store).
// Thread 0 computes the fisheye seed for this map in double (matches jnp
// round-half-to-even exactly; avoids trig via cos(phi)=x/rho, sin(phi)=y/rho).
__global__ void __launch_bounds__(256) hm_kernel(float4* __restrict__ out,
                                                 const float* __restrict__ joint) {
    __shared__ int2 s_seed;

    const unsigned blk  = blockIdx.x;
    const unsigned bj   = blk >> 1;
    const unsigned half = blk & 1u;       // 0: rows 0..127, 1: rows 128..255

    if (threadIdx.x == 0) {
        double x = (double)joint[bj * 3 + 0];
        double y = (double)joint[bj * 3 + 1];
        double z = (double)joint[bj * 3 + 2];
        double rho = sqrt(x * x + y * y);
        double theta = atan2(rho, z);
        double r = 128.0 * theta / 1.5707963267948966;  // RADIUS * theta / (pi/2)
        double cphi, sphi;
        if (rho > 0.0) { cphi = x / rho; sphi = y / rho; }
        else           { cphi = 1.0;     sphi = 0.0;     }
        int sx = (int)rint(128.0 + r * cphi);
        int sy = (int)rint(128.0 + r * sphi);
        sx = min(max(sx, 0), IMG - 1);
        sy = min(max(sy, 0), IMG - 1);
        s_seed = make_int2(sx, sy);
    }
    __syncthreads();
    const int2 s = s_seed;

    const unsigned tid = threadIdx.x;
    const unsigned x0  = (tid & 63u) << 2;      // column of this thread's float4

    // Column weights: invariant across all 32 rows this thread touches.
    float4 wx;
    {
        float* wxp = reinterpret_cast<float*>(&wx);
#pragma unroll
        for (int k = 0; k < 4; k++) {
            int dx  = (int)(x0 + k) - s.x;
            int adx = dx < 0 ? -dx : dx;
            wxp[k] = (adx <= 5) ? c_w[adx] : 0.0f;
        }
    }

    const int    y_first = (int)(half * 128u + (tid >> 6));  // row at k=0; +4 per k
    const size_t base    = (size_t)bj * (IMG * IMG / 4)
                         + (size_t)half * (128 * 64) + tid;

#pragma unroll
    for (int k = 0; k < 32; k++) {
        int y   = y_first + k * 4;
        int dy  = y - s.y;
        int ady = dy < 0 ? -dy : dy;
        float wy = (ady <= 5) ? c_w[ady] : 0.0f;
        float4 v = make_float4(wy * wx.x, wy * wx.y, wy * wx.z, wy * wx.w);
        out[base + (size_t)k * 256] = v;
    }
}

extern "C" void kernel_launch(void* const* d_in, const int* in_sizes, int n_in,
                              void* d_out, int out_size) {
    const float* joint = (const float*)d_in[0];
    // 1344 maps * 2 half-blocks = 2688 blocks of 256 threads
    hm_kernel<<<BJ * 2, 256>>>((float4*)d_out, joint);
}